// round 11
// baseline (speedup 1.0000x reference)
#include <cuda_runtime.h>
#include <float.h>

#define BATCH 2
#define SEQ   4096
#define DIM   384
#define HEADS 6
#define HD    64
#define QK_SCALE 0.125f

__device__ float g_q[BATCH * HEADS * SEQ * HD];
__device__ float g_k[BATCH * HEADS * SEQ * HD];   // pre-rounded tf32 (RNA)
__device__ float g_v[BATCH * HEADS * SEQ * HD];
__device__ float g_kc[BATCH * HEADS * SEQ * HD];  // compacted K
__device__ float g_vc[BATCH * HEADS * SEQ * HD];  // compacted V
__device__ int   g_qidx[BATCH * SEQ];
__device__ int   g_cnt[BATCH];
__device__ float g_vsump[BATCH * HEADS * 8 * HD]; // 8 partials per (b,h)
// pre-split tf32 hi/lo operand buffers
__device__ float g_xh[BATCH * SEQ * DIM],  g_xl[BATCH * SEQ * DIM];
__device__ float g_wqh[3 * DIM * DIM],     g_wql[3 * DIM * DIM];
__device__ float g_wph[DIM * DIM],         g_wpl[DIM * DIM];
__device__ float g_aoh[BATCH * SEQ * DIM], g_aol[BATCH * SEQ * DIM];

__device__ __forceinline__ unsigned tf32_of(float f) {
    unsigned u; asm("cvt.rna.tf32.f32 %0, %1;" : "=r"(u) : "f"(f)); return u;
}
__device__ __forceinline__ float tf32r(float f) { return __uint_as_float(tf32_of(f)); }
__device__ __forceinline__ void mma_tf32(float* c, const unsigned* a, const unsigned* b) {
    asm volatile("mma.sync.aligned.m16n8k8.row.col.f32.tf32.tf32.f32 "
        "{%0,%1,%2,%3}, {%4,%5,%6,%7}, {%8,%9}, {%0,%1,%2,%3};"
        : "+f"(c[0]), "+f"(c[1]), "+f"(c[2]), "+f"(c[3])
        : "r"(a[0]), "r"(a[1]), "r"(a[2]), "r"(a[3]), "r"(b[0]), "r"(b[1]));
}
#define CP16(dst, src) \
    asm volatile("cp.async.cg.shared.global [%0], [%1], 16;" :: \
        "r"((unsigned)__cvta_generic_to_shared(dst)), "l"(src))

// ---------------------------------------------------------------------------
__global__ __launch_bounds__(256) void split_kernel(
    const float4* __restrict__ src, float4* __restrict__ hi,
    float4* __restrict__ lo, int n4)
{
    int i = blockIdx.x * 256 + threadIdx.x;
    if (i >= n4) return;
    float4 v = src[i];
    float4 h, l;
    h.x = tf32r(v.x); l.x = tf32r(v.x - h.x);
    h.y = tf32r(v.y); l.y = tf32r(v.y - h.y);
    h.z = tf32r(v.z); l.z = tf32r(v.z - h.z);
    h.w = tf32r(v.w); l.w = tf32r(v.w - h.w);
    hi[i] = h; lo[i] = l;
}

// ---------------------------------------------------------------------------
// GEMM tf32 x3 on PRE-SPLIT operands (no CVT in mainloop).
// smem (dynamic): AsH[2][128][20] AsL[...] BsH[2][64][20] BsL[...]
// ---------------------------------------------------------------------------
#define AH_OFF 0
#define AL_OFF 5120
#define BH_OFF 10240
#define BL_OFF 12800
#define GEMM_SMEM (15360 * 4)

template<int SEL>
__global__ __launch_bounds__(256, 2) void gemm_tc(
    const float* __restrict__ Ahi, const float* __restrict__ Alo,
    const float* __restrict__ Bhi, const float* __restrict__ Blo,
    const float* __restrict__ bias, float* __restrict__ out)
{
    extern __shared__ __align__(16) float smg[];

    const int bx = blockIdx.x, by = blockIdx.y;
    const int tid = threadIdx.x, wid = tid >> 5, l = tid & 31;
    const int lq = l >> 2, lr = l & 3;
    const int wm = (wid >> 1) * 32, wn = (wid & 1) * 32;
    const int m0 = by * 128, n0 = bx * 64;
    const int lrow = tid >> 2, lkc = (tid & 3) << 2;

    float C[2][4][4] = {};

#define LOAD_STAGE(nb, k0) do { \
    CP16(&smg[AH_OFF + (nb)*2560 + lrow*20 + lkc],        &Ahi[(size_t)(m0+lrow)*DIM + (k0) + lkc]); \
    CP16(&smg[AH_OFF + (nb)*2560 + (lrow+64)*20 + lkc],   &Ahi[(size_t)(m0+lrow+64)*DIM + (k0) + lkc]); \
    CP16(&smg[AL_OFF + (nb)*2560 + lrow*20 + lkc],        &Alo[(size_t)(m0+lrow)*DIM + (k0) + lkc]); \
    CP16(&smg[AL_OFF + (nb)*2560 + (lrow+64)*20 + lkc],   &Alo[(size_t)(m0+lrow+64)*DIM + (k0) + lkc]); \
    CP16(&smg[BH_OFF + (nb)*1280 + lrow*20 + lkc],        &Bhi[(size_t)(n0+lrow)*DIM + (k0) + lkc]); \
    CP16(&smg[BL_OFF + (nb)*1280 + lrow*20 + lkc],        &Blo[(size_t)(n0+lrow)*DIM + (k0) + lkc]); \
    } while (0)

    LOAD_STAGE(0, 0);
    asm volatile("cp.async.commit_group;" ::: "memory");

    const int NITER = DIM / 16;
    for (int it = 0; it < NITER; ++it) {
        if (it + 1 < NITER) {
            LOAD_STAGE((it + 1) & 1, (it + 1) * 16);
            asm volatile("cp.async.commit_group;" ::: "memory");
            asm volatile("cp.async.wait_group 1;" ::: "memory");
        } else {
            asm volatile("cp.async.wait_group 0;" ::: "memory");
        }
        __syncthreads();
        const int buf = it & 1;
        const unsigned* uah = (const unsigned*)&smg[AH_OFF + buf * 2560];
        const unsigned* ual = (const unsigned*)&smg[AL_OFF + buf * 2560];
        const unsigned* ubh = (const unsigned*)&smg[BH_OFF + buf * 1280];
        const unsigned* ubl = (const unsigned*)&smg[BL_OFF + buf * 1280];
#pragma unroll
        for (int ks = 0; ks < 2; ++ks) {
            const int kb = ks * 8;
            unsigned ah[2][4], al[2][4], bh[4][2], bl[4][2];
#pragma unroll
            for (int mt = 0; mt < 2; ++mt) {
                int r0 = (wm + mt * 16 + lq) * 20, r1 = (wm + mt * 16 + lq + 8) * 20;
                ah[mt][0] = uah[r0 + kb + lr];     al[mt][0] = ual[r0 + kb + lr];
                ah[mt][1] = uah[r1 + kb + lr];     al[mt][1] = ual[r1 + kb + lr];
                ah[mt][2] = uah[r0 + kb + lr + 4]; al[mt][2] = ual[r0 + kb + lr + 4];
                ah[mt][3] = uah[r1 + kb + lr + 4]; al[mt][3] = ual[r1 + kb + lr + 4];
            }
#pragma unroll
            for (int nt = 0; nt < 4; ++nt) {
                int r = (wn + nt * 8 + lq) * 20;
                bh[nt][0] = ubh[r + kb + lr];     bl[nt][0] = ubl[r + kb + lr];
                bh[nt][1] = ubh[r + kb + lr + 4]; bl[nt][1] = ubl[r + kb + lr + 4];
            }
#pragma unroll
            for (int mt = 0; mt < 2; ++mt)
#pragma unroll
                for (int nt = 0; nt < 4; ++nt) {
                    mma_tf32(C[mt][nt], al[mt], bh[nt]);
                    mma_tf32(C[mt][nt], ah[mt], bl[nt]);
                    mma_tf32(C[mt][nt], ah[mt], bh[nt]);
                }
        }
        __syncthreads();
    }

    if (SEL == 0) {
        const int sel = bx / HEADS, h = bx % HEADS;
        float* dst = (sel == 0) ? g_q : (sel == 1 ? g_k : g_v);
        const bool rnd = (sel != 0);
#pragma unroll
        for (int mt = 0; mt < 2; ++mt) {
            int m = m0 + wm + mt * 16 + lq;
            float* p = dst + ((size_t)((m >> 12) * HEADS + h) * SEQ + (m & 4095)) * HD;
#pragma unroll
            for (int nt = 0; nt < 4; ++nt) {
                int n = wn + nt * 8 + lr * 2;
                float c0 = C[mt][nt][0], c1 = C[mt][nt][1];
                float c2 = C[mt][nt][2], c3 = C[mt][nt][3];
                if (rnd) { c0 = tf32r(c0); c1 = tf32r(c1); c2 = tf32r(c2); c3 = tf32r(c3); }
                *(float2*)&p[n]          = make_float2(c0, c1);
                *(float2*)&p[8 * HD + n] = make_float2(c2, c3);
            }
        }
    } else {
#pragma unroll
        for (int mt = 0; mt < 2; ++mt) {
            int m = m0 + wm + mt * 16 + lq;
#pragma unroll
            for (int nt = 0; nt < 4; ++nt) {
                int n = n0 + wn + nt * 8 + lr * 2;
                float b0 = bias[n], b1 = bias[n + 1];
                *(float2*)&out[(size_t)m * DIM + n] =
                    make_float2(C[mt][nt][0] + b0, C[mt][nt][1] + b1);
                *(float2*)&out[(size_t)(m + 8) * DIM + n] =
                    make_float2(C[mt][nt][2] + b0, C[mt][nt][3] + b1);
            }
        }
    }
}

// ---------------------------------------------------------------------------
__global__ __launch_bounds__(1024) void compact_kernel(const int* __restrict__ mask)
{
    __shared__ int sdata[1024];
    __shared__ int base;
    const int b = blockIdx.x, t = threadIdx.x;
    if (t == 0) base = 0;
    __syncthreads();
    for (int pass = 0; pass < SEQ / 1024; ++pass) {
        int n = pass * 1024 + t;
        int m = (mask[b * SEQ + n] != 0) ? 1 : 0;
        sdata[t] = m;
        __syncthreads();
        for (int off = 1; off < 1024; off <<= 1) {
            int v = (t >= off) ? sdata[t - off] : 0;
            __syncthreads();
            if (t >= off) sdata[t] += v;
            __syncthreads();
        }
        if (m) g_qidx[b * SEQ + base + sdata[t] - 1] = n;
        __syncthreads();
        if (t == 1023) base += sdata[1023];
        __syncthreads();
    }
    if (t == 0) g_cnt[b] = base;
}

__global__ __launch_bounds__(256) void gather_kernel()
{
    const int bh = blockIdx.x, tile = blockIdx.y;
    const int b = bh / HEADS;
    const int cnt = g_cnt[b];
    const int padded = (cnt + 63) & ~63;
    if (tile * 64 >= padded) return;
    const int t = threadIdx.x;
    const int row = tile * 64 + (t >> 2);
    const int seg = (t & 3) * 16;
    const float* kb = g_k + (size_t)bh * SEQ * HD;
    const float* vb = g_v + (size_t)bh * SEQ * HD;
    float* kc = g_kc + (size_t)bh * SEQ * HD;
    float* vc = g_vc + (size_t)bh * SEQ * HD;
    float4 kv[4], vv[4];
    if (row < cnt) {
        const int src = g_qidx[b * SEQ + row];
#pragma unroll
        for (int u = 0; u < 4; ++u) {
            kv[u] = *(const float4*)&kb[(size_t)src * HD + seg + u * 4];
            vv[u] = *(const float4*)&vb[(size_t)src * HD + seg + u * 4];
        }
    } else {
#pragma unroll
        for (int u = 0; u < 4; ++u) {
            kv[u] = make_float4(0.f, 0.f, 0.f, 0.f);
            vv[u] = make_float4(0.f, 0.f, 0.f, 0.f);
        }
    }
#pragma unroll
    for (int u = 0; u < 4; ++u) {
        *(float4*)&kc[(size_t)row * HD + seg + u * 4] = kv[u];
        *(float4*)&vc[(size_t)row * HD + seg + u * 4] = vv[u];
    }
}

// vsum partials: grid (12, 8), each block sums 512 rows.
__global__ __launch_bounds__(256) void vsum_kernel()
{
    __shared__ float sdata[256];
    const int bh = blockIdx.x, part = blockIdx.y;
    const int t = threadIdx.x;
    const int d = t & 63, g = t >> 6;     // 4 groups
    const float* vb = g_v + (size_t)bh * SEQ * HD;
    float s = 0.f;
    const int r0 = part * 512;
    for (int n = r0 + g; n < r0 + 512; n += 4) s += vb[(size_t)n * HD + d];
    sdata[t] = s;
    __syncthreads();
    if (g == 0)
        g_vsump[(bh * 8 + part) * HD + d] =
            sdata[d] + sdata[64 + d] + sdata[128 + d] + sdata[192 + d];
}

// Dead rows -> ao hi/lo = split(vsum/SEQ).
__global__ __launch_bounds__(256) void fill_dead_kernel(const int* __restrict__ mask)
{
    __shared__ float vsh[DIM], vsl[DIM];
    const int b = blockIdx.x, tile = blockIdx.y;
    const int t = threadIdx.x;
    const float inv = 1.0f / SEQ;
    for (int c = t; c < DIM; c += 256) {
        int bh = b * HEADS + (c >> 6), d = c & 63;
        float s = 0.f;
#pragma unroll
        for (int p = 0; p < 8; ++p) s += g_vsump[(bh * 8 + p) * HD + d];
        float v = s * inv;
        float h = tf32r(v);
        vsh[c] = h; vsl[c] = tf32r(v - h);
    }
    __syncthreads();
    for (int c = t; c < 64 * DIM; c += 256) {
        int row = tile * 64 + c / DIM;
        int col = c % DIM;
        if (mask[b * SEQ + row] != 0) continue;
        size_t idx = ((size_t)b * SEQ + row) * DIM + col;
        g_aoh[idx] = vsh[col];
        g_aol[idx] = vsl[col];
    }
}

// ---------------------------------------------------------------------------
// Flash attention over compacted rows/keys (unchanged math); epilogue writes
// pre-split ao hi/lo for the proj GEMM.
// ---------------------------------------------------------------------------
#define KS_F (64 * 68)
#define VS_F (64 * 72)
#define STG  (KS_F + VS_F)
#define ATTN_SMEM_BYTES (3 * STG * 4)

__global__ __launch_bounds__(256, 2) void attn_kernel()
{
    extern __shared__ __align__(16) float sm[];

    const int qt = blockIdx.x, bh = blockIdx.y;
    const int b = bh / HEADS, h = bh % HEADS;
    const int cnt = g_cnt[b];
    if (qt * 128 >= cnt) return;

    const int tid = threadIdx.x, w = tid >> 5, l = tid & 31;
    const int lq = l >> 2, lr = l & 3;

    const float* qbase = g_q + (size_t)bh * SEQ * HD;
    const float* kbase = g_kc + (size_t)bh * SEQ * HD;
    const float* vbase = g_vc + (size_t)bh * SEQ * HD;

    const int qrow0 = qt * 128 + w * 16 + lq;
    const int qrow1 = qrow0 + 8;
    const int ridx0 = g_qidx[b * SEQ + (qrow0 < cnt ? qrow0 : 0)];
    const int ridx1 = g_qidx[b * SEQ + (qrow1 < cnt ? qrow1 : 0)];

    const int crow = tid >> 2;
    const int cbase = (tid & 3) * 16;

    unsigned aQ[8][4];
#pragma unroll
    for (int kk = 0; kk < 8; ++kk) {
        aQ[kk][0] = tf32_of(qbase[(size_t)ridx0 * HD + kk * 8 + lr] * QK_SCALE);
        aQ[kk][1] = tf32_of(qbase[(size_t)ridx1 * HD + kk * 8 + lr] * QK_SCALE);
        aQ[kk][2] = tf32_of(qbase[(size_t)ridx0 * HD + kk * 8 + lr + 4] * QK_SCALE);
        aQ[kk][3] = tf32_of(qbase[(size_t)ridx1 * HD + kk * 8 + lr + 4] * QK_SCALE);
    }

    float O[8][4] = {};
    float m0 = -FLT_MAX, m1 = -FLT_MAX, l0 = 0.f, l1 = 0.f;

    const int NT = (cnt + 63) >> 6;

    {
        float* ks = sm; float* vs = sm + KS_F;
#pragma unroll
        for (int u = 0; u < 4; ++u) {
            int off = cbase + u * 4;
            CP16(&ks[crow * 68 + off], &kbase[(size_t)crow * HD + off]);
            CP16(&vs[crow * 72 + off], &vbase[(size_t)crow * HD + off]);
        }
        asm volatile("cp.async.commit_group;" ::: "memory");
    }

    for (int kt = 0; kt < NT; ++kt) {
        const int s = kt % 3;
        const float* ksf = sm + s * STG;
        const unsigned* ku = (const unsigned*)ksf;
        const unsigned* vu = (const unsigned*)(ksf + KS_F);

        if (kt + 1 < NT) {
            float* ks2 = sm + ((kt + 1) % 3) * STG;
            float* vs2 = ks2 + KS_F;
            const size_t nb = (size_t)(kt + 1) * 64;
#pragma unroll
            for (int u = 0; u < 4; ++u) {
                int off = cbase + u * 4;
                CP16(&ks2[crow * 68 + off], &kbase[(nb + crow) * HD + off]);
                CP16(&vs2[crow * 72 + off], &vbase[(nb + crow) * HD + off]);
            }
            asm volatile("cp.async.commit_group;" ::: "memory");
            asm volatile("cp.async.wait_group 1;" ::: "memory");
        } else {
            asm volatile("cp.async.wait_group 0;" ::: "memory");
        }
        __syncthreads();

        float sc[8][4];
#pragma unroll
        for (int nt = 0; nt < 8; ++nt) {
            sc[nt][0] = sc[nt][1] = sc[nt][2] = sc[nt][3] = 0.f;
            const unsigned* krow = ku + (nt * 8 + lq) * 68;
#pragma unroll
            for (int kk = 0; kk < 8; ++kk) {
                unsigned bk[2] = {krow[kk * 8 + lr], krow[kk * 8 + lr + 4]};
                mma_tf32(sc[nt], aQ[kk], bk);
            }
        }

        const int ktbase = kt * 64;
        float t0 = -FLT_MAX, t1 = -FLT_MAX;
#pragma unroll
        for (int nt = 0; nt < 8; ++nt) {
            int c0 = ktbase + nt * 8 + lr * 2;
            bool v0 = c0 < cnt, v1 = (c0 + 1) < cnt;
            if (!v0) { sc[nt][0] = -FLT_MAX; sc[nt][2] = -FLT_MAX; }
            if (!v1) { sc[nt][1] = -FLT_MAX; sc[nt][3] = -FLT_MAX; }
            t0 = fmaxf(t0, fmaxf(sc[nt][0], sc[nt][1]));
            t1 = fmaxf(t1, fmaxf(sc[nt][2], sc[nt][3]));
        }
        t0 = fmaxf(t0, __shfl_xor_sync(0xffffffffu, t0, 1));
        t0 = fmaxf(t0, __shfl_xor_sync(0xffffffffu, t0, 2));
        t1 = fmaxf(t1, __shfl_xor_sync(0xffffffffu, t1, 1));
        t1 = fmaxf(t1, __shfl_xor_sync(0xffffffffu, t1, 2));

        float mn0 = fmaxf(m0, t0), mn1 = fmaxf(m1, t1);
        float al0 = __expf(m0 - mn0), al1 = __expf(m1 - mn1);
        m0 = mn0; m1 = mn1;

        float ps0 = 0.f, ps1 = 0.f;
#pragma unroll
        for (int nt = 0; nt < 8; ++nt) {
            sc[nt][0] = __expf(sc[nt][0] - mn0);
            sc[nt][1] = __expf(sc[nt][1] - mn0);
            sc[nt][2] = __expf(sc[nt][2] - mn1);
            sc[nt][3] = __expf(sc[nt][3] - mn1);
            ps0 += sc[nt][0] + sc[nt][1];
            ps1 += sc[nt][2] + sc[nt][3];
        }
        ps0 += __shfl_xor_sync(0xffffffffu, ps0, 1);
        ps0 += __shfl_xor_sync(0xffffffffu, ps0, 2);
        ps1 += __shfl_xor_sync(0xffffffffu, ps1, 1);
        ps1 += __shfl_xor_sync(0xffffffffu, ps1, 2);
        l0 = l0 * al0 + ps0;
        l1 = l1 * al1 + ps1;

#pragma unroll
        for (int nt = 0; nt < 8; ++nt) {
            O[nt][0] *= al0; O[nt][1] *= al0;
            O[nt][2] *= al1; O[nt][3] *= al1;
        }

        const int srcA = (l & ~3) + (lr >> 1);
        const bool par = (lr & 1) != 0;
#pragma unroll
        for (int kk = 0; kk < 8; ++kk) {
            float x0 = __shfl_sync(0xffffffffu, sc[kk][0], srcA);
            float x1 = __shfl_sync(0xffffffffu, sc[kk][1], srcA);
            float x2 = __shfl_sync(0xffffffffu, sc[kk][2], srcA);
            float x3 = __shfl_sync(0xffffffffu, sc[kk][3], srcA);
            float y0 = __shfl_sync(0xffffffffu, sc[kk][0], srcA + 2);
            float y1 = __shfl_sync(0xffffffffu, sc[kk][1], srcA + 2);
            float y2 = __shfl_sync(0xffffffffu, sc[kk][2], srcA + 2);
            float y3 = __shfl_sync(0xffffffffu, sc[kk][3], srcA + 2);
            unsigned aP[4];
            aP[0] = tf32_of(par ? x1 : x0);
            aP[1] = tf32_of(par ? x3 : x2);
            aP[2] = tf32_of(par ? y1 : y0);
            aP[3] = tf32_of(par ? y3 : y2);
            const unsigned* vr0 = vu + (kk * 8 + lr) * 72;
            const unsigned* vr1 = vu + (kk * 8 + lr + 4) * 72;
#pragma unroll
            for (int nt = 0; nt < 8; ++nt) {
                unsigned bv[2] = {vr0[nt * 8 + lq], vr1[nt * 8 + lq]};
                mma_tf32(O[nt], aP, bv);
            }
        }
    }

    const float inv0 = 1.f / l0, inv1 = 1.f / l1;
    if (qrow0 < cnt) {
        size_t base = ((size_t)b * SEQ + ridx0) * DIM + h * HD;
#pragma unroll
        for (int nt = 0; nt < 8; ++nt) {
            int c = nt * 8 + lr * 2;
            float v0 = O[nt][0] * inv0, v1 = O[nt][1] * inv0;
            float h0 = tf32r(v0), h1 = tf32r(v1);
            *(float2*)&g_aoh[base + c] = make_float2(h0, h1);
            *(float2*)&g_aol[base + c] = make_float2(tf32r(v0 - h0), tf32r(v1 - h1));
        }
    }
    if (qrow1 < cnt) {
        size_t base = ((size_t)b * SEQ + ridx1) * DIM + h * HD;
#pragma unroll
        for (int nt = 0; nt < 8; ++nt) {
            int c = nt * 8 + lr * 2;
            float v0 = O[nt][2] * inv1, v1 = O[nt][3] * inv1;
            float h0 = tf32r(v0), h1 = tf32r(v1);
            *(float2*)&g_aoh[base + c] = make_float2(h0, h1);
            *(float2*)&g_aol[base + c] = make_float2(tf32r(v0 - h0), tf32r(v1 - h1));
        }
    }
}

// ---------------------------------------------------------------------------
extern "C" void kernel_launch(void* const* d_in, const int* in_sizes, int n_in,
                              void* d_out, int out_size)
{
    const float* x      = (const float*)d_in[0];
    const int*   mask   = (const int*)d_in[1];
    const float* w_qkv  = (const float*)d_in[2];
    const float* w_proj = (const float*)d_in[3];
    const float* b_proj = (const float*)d_in[4];
    float*       out    = (float*)d_out;

    cudaFuncSetAttribute(attn_kernel,
        cudaFuncAttributeMaxDynamicSharedMemorySize, ATTN_SMEM_BYTES);
    cudaFuncSetAttribute(gemm_tc<0>,
        cudaFuncAttributeMaxDynamicSharedMemorySize, GEMM_SMEM);
    cudaFuncSetAttribute(gemm_tc<1>,
        cudaFuncAttributeMaxDynamicSharedMemorySize, GEMM_SMEM);

    // pre-split operands into tf32 hi/lo
    float *xh, *xl, *wqh, *wql, *wph, *wpl;
    cudaGetSymbolAddress((void**)&xh,  g_xh);  cudaGetSymbolAddress((void**)&xl,  g_xl);
    cudaGetSymbolAddress((void**)&wqh, g_wqh); cudaGetSymbolAddress((void**)&wql, g_wql);
    cudaGetSymbolAddress((void**)&wph, g_wph); cudaGetSymbolAddress((void**)&wpl, g_wpl);

    int n4x = BATCH * SEQ * DIM / 4, n4q = 3 * DIM * DIM / 4, n4p = DIM * DIM / 4;
    split_kernel<<<(n4x + 255) / 256, 256>>>((const float4*)x, (float4*)xh, (float4*)xl, n4x);
    split_kernel<<<(n4q + 255) / 256, 256>>>((const float4*)w_qkv, (float4*)wqh, (float4*)wql, n4q);
    split_kernel<<<(n4p + 255) / 256, 256>>>((const float4*)w_proj, (float4*)wph, (float4*)wpl, n4p);

    dim3 g1(3 * DIM / 64, (BATCH * SEQ) / 128);
    gemm_tc<0><<<g1, 256, GEMM_SMEM>>>(xh, xl, wqh, wql, nullptr, nullptr);

    compact_kernel<<<BATCH, 1024>>>(mask);
    gather_kernel<<<dim3(BATCH * HEADS, SEQ / 64), 256>>>();
    vsum_kernel<<<dim3(BATCH * HEADS, 8), 256>>>();

    dim3 g2(SEQ / 128, BATCH * HEADS);
    attn_kernel<<<g2, 256, ATTN_SMEM_BYTES>>>();

    fill_dead_kernel<<<dim3(BATCH, SEQ / 64), 256>>>(mask);

    float *aoh, *aol;
    cudaGetSymbolAddress((void**)&aoh, g_aoh);
    cudaGetSymbolAddress((void**)&aol, g_aol);
    dim3 g3(DIM / 64, (BATCH * SEQ) / 128);
    gemm_tc<1><<<g3, 256, GEMM_SMEM>>>(aoh, aol, wph, wpl, b_proj, out);
}

// round 12
// speedup vs baseline: 1.1073x; 1.1073x over previous
#include <cuda_runtime.h>
#include <float.h>

#define BATCH 2
#define SEQ   4096
#define DIM   384
#define HEADS 6
#define HD    64
#define QK_SCALE 0.125f

__device__ float g_q[BATCH * HEADS * SEQ * HD];
__device__ float g_k[BATCH * HEADS * SEQ * HD];   // pre-rounded tf32 (RNA)
__device__ float g_v[BATCH * HEADS * SEQ * HD];   // pre-rounded tf32 (RNA)
__device__ float g_kc[BATCH * HEADS * SEQ * HD];  // compacted K
__device__ float g_vc[BATCH * HEADS * SEQ * HD];  // compacted V
__device__ float g_ao[BATCH * SEQ * DIM];
__device__ int   g_qidx[BATCH * SEQ];
__device__ int   g_cnt[BATCH];
__device__ float g_vsump[BATCH * HEADS * 8 * HD]; // 8 partials per (b,h)

__device__ __forceinline__ unsigned tf32_of(float f) {
    unsigned u; asm("cvt.rna.tf32.f32 %0, %1;" : "=r"(u) : "f"(f)); return u;
}
__device__ __forceinline__ float tf32r(float f) { return __uint_as_float(tf32_of(f)); }
__device__ __forceinline__ void mma_tf32(float* c, const unsigned* a, const unsigned* b) {
    asm volatile("mma.sync.aligned.m16n8k8.row.col.f32.tf32.tf32.f32 "
        "{%0,%1,%2,%3}, {%4,%5,%6,%7}, {%8,%9}, {%0,%1,%2,%3};"
        : "+f"(c[0]), "+f"(c[1]), "+f"(c[2]), "+f"(c[3])
        : "r"(a[0]), "r"(a[1]), "r"(a[2]), "r"(a[3]), "r"(b[0]), "r"(b[1]));
}
#define CP16(dst, src) \
    asm volatile("cp.async.cg.shared.global [%0], [%1], 16;" :: \
        "r"((unsigned)__cvta_generic_to_shared(dst)), "l"(src))

// ---------------------------------------------------------------------------
// GEMM (tf32 x3, inline split) — the measured-154us round-10 version.
// SEL=0: qkv -> g_q/g_k/g_v (K,V RNA-rounded).  SEL=1: out = g_ao@w^T + bias.
// ---------------------------------------------------------------------------
template<int SEL>
__global__ __launch_bounds__(256, 2) void gemm_tc(
    const float* __restrict__ Ax, const float* __restrict__ w,
    const float* __restrict__ bias, float* __restrict__ out)
{
    __shared__ __align__(16) float As[2][128][20];
    __shared__ __align__(16) float Bs[2][64][20];

    const float* A = (SEL == 0) ? Ax : g_ao;

    const int bx = blockIdx.x, by = blockIdx.y;
    const int tid = threadIdx.x, wid = tid >> 5, l = tid & 31;
    const int lq = l >> 2, lr = l & 3;
    const int wm = (wid >> 1) * 32, wn = (wid & 1) * 32;
    const int m0 = by * 128, n0 = bx * 64;
    const int lrow = tid >> 2, lkc = (tid & 3) << 2;

    float C[2][4][4] = {};

    CP16(&As[0][lrow][lkc],      &A[(size_t)(m0 + lrow) * DIM + lkc]);
    CP16(&As[0][lrow + 64][lkc], &A[(size_t)(m0 + lrow + 64) * DIM + lkc]);
    CP16(&Bs[0][lrow][lkc],      &w[(size_t)(n0 + lrow) * DIM + lkc]);
    asm volatile("cp.async.commit_group;" ::: "memory");

    const int NITER = DIM / 16;
    for (int it = 0; it < NITER; ++it) {
        if (it + 1 < NITER) {
            int k0 = (it + 1) * 16, nb = (it + 1) & 1;
            CP16(&As[nb][lrow][lkc],      &A[(size_t)(m0 + lrow) * DIM + k0 + lkc]);
            CP16(&As[nb][lrow + 64][lkc], &A[(size_t)(m0 + lrow + 64) * DIM + k0 + lkc]);
            CP16(&Bs[nb][lrow][lkc],      &w[(size_t)(n0 + lrow) * DIM + k0 + lkc]);
            asm volatile("cp.async.commit_group;" ::: "memory");
            asm volatile("cp.async.wait_group 1;" ::: "memory");
        } else {
            asm volatile("cp.async.wait_group 0;" ::: "memory");
        }
        __syncthreads();
        const int buf = it & 1;
#pragma unroll
        for (int ks = 0; ks < 2; ++ks) {
            const int kb = ks * 8;
            unsigned ah[2][4], al[2][4], bh[4][2], bl[4][2];
#pragma unroll
            for (int mt = 0; mt < 2; ++mt) {
                float a0 = As[buf][wm + mt * 16 + lq][kb + lr];
                float a1 = As[buf][wm + mt * 16 + lq + 8][kb + lr];
                float a2 = As[buf][wm + mt * 16 + lq][kb + lr + 4];
                float a3 = As[buf][wm + mt * 16 + lq + 8][kb + lr + 4];
                ah[mt][0] = tf32_of(a0); al[mt][0] = tf32_of(a0 - __uint_as_float(ah[mt][0]));
                ah[mt][1] = tf32_of(a1); al[mt][1] = tf32_of(a1 - __uint_as_float(ah[mt][1]));
                ah[mt][2] = tf32_of(a2); al[mt][2] = tf32_of(a2 - __uint_as_float(ah[mt][2]));
                ah[mt][3] = tf32_of(a3); al[mt][3] = tf32_of(a3 - __uint_as_float(ah[mt][3]));
            }
#pragma unroll
            for (int nt = 0; nt < 4; ++nt) {
                float b0 = Bs[buf][wn + nt * 8 + lq][kb + lr];
                float b1 = Bs[buf][wn + nt * 8 + lq][kb + lr + 4];
                bh[nt][0] = tf32_of(b0); bl[nt][0] = tf32_of(b0 - __uint_as_float(bh[nt][0]));
                bh[nt][1] = tf32_of(b1); bl[nt][1] = tf32_of(b1 - __uint_as_float(bh[nt][1]));
            }
#pragma unroll
            for (int mt = 0; mt < 2; ++mt)
#pragma unroll
                for (int nt = 0; nt < 4; ++nt) {
                    mma_tf32(C[mt][nt], al[mt], bh[nt]);
                    mma_tf32(C[mt][nt], ah[mt], bl[nt]);
                    mma_tf32(C[mt][nt], ah[mt], bh[nt]);
                }
        }
        __syncthreads();
    }

    if (SEL == 0) {
        const int sel = bx / HEADS, h = bx % HEADS;
        float* dst = (sel == 0) ? g_q : (sel == 1 ? g_k : g_v);
        const bool rnd = (sel != 0);
#pragma unroll
        for (int mt = 0; mt < 2; ++mt) {
            int m = m0 + wm + mt * 16 + lq;
            float* p = dst + ((size_t)((m >> 12) * HEADS + h) * SEQ + (m & 4095)) * HD;
#pragma unroll
            for (int nt = 0; nt < 4; ++nt) {
                int n = wn + nt * 8 + lr * 2;
                float c0 = C[mt][nt][0], c1 = C[mt][nt][1];
                float c2 = C[mt][nt][2], c3 = C[mt][nt][3];
                if (rnd) { c0 = tf32r(c0); c1 = tf32r(c1); c2 = tf32r(c2); c3 = tf32r(c3); }
                *(float2*)&p[n]          = make_float2(c0, c1);
                *(float2*)&p[8 * HD + n] = make_float2(c2, c3);
            }
        }
    } else {
#pragma unroll
        for (int mt = 0; mt < 2; ++mt) {
            int m = m0 + wm + mt * 16 + lq;
#pragma unroll
            for (int nt = 0; nt < 4; ++nt) {
                int n = n0 + wn + nt * 8 + lr * 2;
                float b0 = bias[n], b1 = bias[n + 1];
                *(float2*)&out[(size_t)m * DIM + n] =
                    make_float2(C[mt][nt][0] + b0, C[mt][nt][1] + b1);
                *(float2*)&out[(size_t)(m + 8) * DIM + n] =
                    make_float2(C[mt][nt][2] + b0, C[mt][nt][3] + b1);
            }
        }
    }
}

// ---------------------------------------------------------------------------
// Compaction: ballot/popc warp scan (deterministic), 1024 threads, 4 passes.
// ---------------------------------------------------------------------------
__global__ __launch_bounds__(1024) void compact_kernel(const int* __restrict__ mask)
{
    __shared__ int wsum[32];
    __shared__ int base;
    const int b = blockIdx.x, t = threadIdx.x;
    const int wid = t >> 5, lane = t & 31;
    if (t == 0) base = 0;
    __syncthreads();
    for (int pass = 0; pass < SEQ / 1024; ++pass) {
        int n = pass * 1024 + t;
        int m = (mask[b * SEQ + n] != 0) ? 1 : 0;
        unsigned bal = __ballot_sync(0xffffffffu, m);
        int wpre = __popc(bal & ((1u << lane) - 1u));
        if (lane == 0) wsum[wid] = __popc(bal);
        __syncthreads();
        if (wid == 0) {
            int v = wsum[lane];
#pragma unroll
            for (int off = 1; off < 32; off <<= 1) {
                int u = __shfl_up_sync(0xffffffffu, v, off);
                if (lane >= off) v += u;
            }
            wsum[lane] = v;
        }
        __syncthreads();
        int pre = (wid > 0 ? wsum[wid - 1] : 0) + wpre;
        if (m) g_qidx[b * SEQ + base + pre] = n;
        __syncthreads();
        if (t == 0) base += wsum[31];
        __syncthreads();
    }
    if (t == 0) g_cnt[b] = base;
}

// ---------------------------------------------------------------------------
// Gather live K/V rows into compacted buffers; zero-pad to 64-row boundary.
// ---------------------------------------------------------------------------
__global__ __launch_bounds__(256) void gather_kernel()
{
    const int bh = blockIdx.x, tile = blockIdx.y;
    const int b = bh / HEADS;
    const int cnt = g_cnt[b];
    const int padded = (cnt + 63) & ~63;
    if (tile * 64 >= padded) return;
    const int t = threadIdx.x;
    const int row = tile * 64 + (t >> 2);
    const int seg = (t & 3) * 16;
    const float* kb = g_k + (size_t)bh * SEQ * HD;
    const float* vb = g_v + (size_t)bh * SEQ * HD;
    float* kc = g_kc + (size_t)bh * SEQ * HD;
    float* vc = g_vc + (size_t)bh * SEQ * HD;
    float4 kv[4], vv[4];
    if (row < cnt) {
        const int src = g_qidx[b * SEQ + row];
#pragma unroll
        for (int u = 0; u < 4; ++u) {
            kv[u] = *(const float4*)&kb[(size_t)src * HD + seg + u * 4];
            vv[u] = *(const float4*)&vb[(size_t)src * HD + seg + u * 4];
        }
    } else {
#pragma unroll
        for (int u = 0; u < 4; ++u) {
            kv[u] = make_float4(0.f, 0.f, 0.f, 0.f);
            vv[u] = make_float4(0.f, 0.f, 0.f, 0.f);
        }
    }
#pragma unroll
    for (int u = 0; u < 4; ++u) {
        *(float4*)&kc[(size_t)row * HD + seg + u * 4] = kv[u];
        *(float4*)&vc[(size_t)row * HD + seg + u * 4] = vv[u];
    }
}

// vsum partials: grid (12, 8), each block sums 512 rows (verified round 11).
__global__ __launch_bounds__(256) void vsum_kernel()
{
    __shared__ float sdata[256];
    const int bh = blockIdx.x, part = blockIdx.y;
    const int t = threadIdx.x;
    const int d = t & 63, g = t >> 6;     // 4 groups
    const float* vb = g_v + (size_t)bh * SEQ * HD;
    float s = 0.f;
    const int r0 = part * 512;
    for (int n = r0 + g; n < r0 + 512; n += 4) s += vb[(size_t)n * HD + d];
    sdata[t] = s;
    __syncthreads();
    if (g == 0)
        g_vsump[(bh * 8 + part) * HD + d] =
            sdata[d] + sdata[64 + d] + sdata[128 + d] + sdata[192 + d];
}

// Dead rows -> g_ao = vsum / SEQ  (reduce the 8 partials here).
__global__ __launch_bounds__(256) void fill_dead_kernel(const int* __restrict__ mask)
{
    __shared__ float vsh[DIM];
    const int b = blockIdx.x, tile = blockIdx.y;
    const int t = threadIdx.x;
    const float inv = 1.0f / SEQ;
    for (int c = t; c < DIM; c += 256) {
        int bh = b * HEADS + (c >> 6), d = c & 63;
        float s = 0.f;
#pragma unroll
        for (int p = 0; p < 8; ++p) s += g_vsump[(bh * 8 + p) * HD + d];
        vsh[c] = s * inv;
    }
    __syncthreads();
    for (int c = t; c < 64 * DIM; c += 256) {
        int row = tile * 64 + c / DIM;
        int col = c % DIM;
        if (mask[b * SEQ + row] != 0) continue;
        g_ao[((size_t)b * SEQ + row) * DIM + col] = vsh[col];
    }
}

// ---------------------------------------------------------------------------
// Flash attention over compacted rows/keys (round-10 version, measured good).
// ---------------------------------------------------------------------------
#define KS_F (64 * 68)
#define VS_F (64 * 72)
#define STG  (KS_F + VS_F)
#define ATTN_SMEM_BYTES (3 * STG * 4)

__global__ __launch_bounds__(256, 2) void attn_kernel()
{
    extern __shared__ __align__(16) float sm[];

    const int qt = blockIdx.x, bh = blockIdx.y;
    const int b = bh / HEADS, h = bh % HEADS;
    const int cnt = g_cnt[b];
    if (qt * 128 >= cnt) return;

    const int tid = threadIdx.x, w = tid >> 5, l = tid & 31;
    const int lq = l >> 2, lr = l & 3;

    const float* qbase = g_q + (size_t)bh * SEQ * HD;
    const float* kbase = g_kc + (size_t)bh * SEQ * HD;
    const float* vbase = g_vc + (size_t)bh * SEQ * HD;

    const int qrow0 = qt * 128 + w * 16 + lq;
    const int qrow1 = qrow0 + 8;
    const int ridx0 = g_qidx[b * SEQ + (qrow0 < cnt ? qrow0 : 0)];
    const int ridx1 = g_qidx[b * SEQ + (qrow1 < cnt ? qrow1 : 0)];

    const int crow = tid >> 2;
    const int cbase = (tid & 3) * 16;

    unsigned aQ[8][4];
#pragma unroll
    for (int kk = 0; kk < 8; ++kk) {
        aQ[kk][0] = tf32_of(qbase[(size_t)ridx0 * HD + kk * 8 + lr] * QK_SCALE);
        aQ[kk][1] = tf32_of(qbase[(size_t)ridx1 * HD + kk * 8 + lr] * QK_SCALE);
        aQ[kk][2] = tf32_of(qbase[(size_t)ridx0 * HD + kk * 8 + lr + 4] * QK_SCALE);
        aQ[kk][3] = tf32_of(qbase[(size_t)ridx1 * HD + kk * 8 + lr + 4] * QK_SCALE);
    }

    float O[8][4] = {};
    float m0 = -FLT_MAX, m1 = -FLT_MAX, l0 = 0.f, l1 = 0.f;

    const int NT = (cnt + 63) >> 6;

    {
        float* ks = sm; float* vs = sm + KS_F;
#pragma unroll
        for (int u = 0; u < 4; ++u) {
            int off = cbase + u * 4;
            CP16(&ks[crow * 68 + off], &kbase[(size_t)crow * HD + off]);
            CP16(&vs[crow * 72 + off], &vbase[(size_t)crow * HD + off]);
        }
        asm volatile("cp.async.commit_group;" ::: "memory");
    }

    for (int kt = 0; kt < NT; ++kt) {
        const int s = kt % 3;
        const float* ksf = sm + s * STG;
        const unsigned* ku = (const unsigned*)ksf;
        const unsigned* vu = (const unsigned*)(ksf + KS_F);

        if (kt + 1 < NT) {
            float* ks2 = sm + ((kt + 1) % 3) * STG;
            float* vs2 = ks2 + KS_F;
            const size_t nb = (size_t)(kt + 1) * 64;
#pragma unroll
            for (int u = 0; u < 4; ++u) {
                int off = cbase + u * 4;
                CP16(&ks2[crow * 68 + off], &kbase[(nb + crow) * HD + off]);
                CP16(&vs2[crow * 72 + off], &vbase[(nb + crow) * HD + off]);
            }
            asm volatile("cp.async.commit_group;" ::: "memory");
            asm volatile("cp.async.wait_group 1;" ::: "memory");
        } else {
            asm volatile("cp.async.wait_group 0;" ::: "memory");
        }
        __syncthreads();

        float sc[8][4];
#pragma unroll
        for (int nt = 0; nt < 8; ++nt) {
            sc[nt][0] = sc[nt][1] = sc[nt][2] = sc[nt][3] = 0.f;
            const unsigned* krow = ku + (nt * 8 + lq) * 68;
#pragma unroll
            for (int kk = 0; kk < 8; ++kk) {
                unsigned bk[2] = {krow[kk * 8 + lr], krow[kk * 8 + lr + 4]};
                mma_tf32(sc[nt], aQ[kk], bk);
            }
        }

        const int ktbase = kt * 64;
        float t0 = -FLT_MAX, t1 = -FLT_MAX;
#pragma unroll
        for (int nt = 0; nt < 8; ++nt) {
            int c0 = ktbase + nt * 8 + lr * 2;
            bool v0 = c0 < cnt, v1 = (c0 + 1) < cnt;
            if (!v0) { sc[nt][0] = -FLT_MAX; sc[nt][2] = -FLT_MAX; }
            if (!v1) { sc[nt][1] = -FLT_MAX; sc[nt][3] = -FLT_MAX; }
            t0 = fmaxf(t0, fmaxf(sc[nt][0], sc[nt][1]));
            t1 = fmaxf(t1, fmaxf(sc[nt][2], sc[nt][3]));
        }
        t0 = fmaxf(t0, __shfl_xor_sync(0xffffffffu, t0, 1));
        t0 = fmaxf(t0, __shfl_xor_sync(0xffffffffu, t0, 2));
        t1 = fmaxf(t1, __shfl_xor_sync(0xffffffffu, t1, 1));
        t1 = fmaxf(t1, __shfl_xor_sync(0xffffffffu, t1, 2));

        float mn0 = fmaxf(m0, t0), mn1 = fmaxf(m1, t1);
        float al0 = __expf(m0 - mn0), al1 = __expf(m1 - mn1);
        m0 = mn0; m1 = mn1;

        float ps0 = 0.f, ps1 = 0.f;
#pragma unroll
        for (int nt = 0; nt < 8; ++nt) {
            sc[nt][0] = __expf(sc[nt][0] - mn0);
            sc[nt][1] = __expf(sc[nt][1] - mn0);
            sc[nt][2] = __expf(sc[nt][2] - mn1);
            sc[nt][3] = __expf(sc[nt][3] - mn1);
            ps0 += sc[nt][0] + sc[nt][1];
            ps1 += sc[nt][2] + sc[nt][3];
        }
        ps0 += __shfl_xor_sync(0xffffffffu, ps0, 1);
        ps0 += __shfl_xor_sync(0xffffffffu, ps0, 2);
        ps1 += __shfl_xor_sync(0xffffffffu, ps1, 1);
        ps1 += __shfl_xor_sync(0xffffffffu, ps1, 2);
        l0 = l0 * al0 + ps0;
        l1 = l1 * al1 + ps1;

#pragma unroll
        for (int nt = 0; nt < 8; ++nt) {
            O[nt][0] *= al0; O[nt][1] *= al0;
            O[nt][2] *= al1; O[nt][3] *= al1;
        }

        const int srcA = (l & ~3) + (lr >> 1);
        const bool par = (lr & 1) != 0;
#pragma unroll
        for (int kk = 0; kk < 8; ++kk) {
            float x0 = __shfl_sync(0xffffffffu, sc[kk][0], srcA);
            float x1 = __shfl_sync(0xffffffffu, sc[kk][1], srcA);
            float x2 = __shfl_sync(0xffffffffu, sc[kk][2], srcA);
            float x3 = __shfl_sync(0xffffffffu, sc[kk][3], srcA);
            float y0 = __shfl_sync(0xffffffffu, sc[kk][0], srcA + 2);
            float y1 = __shfl_sync(0xffffffffu, sc[kk][1], srcA + 2);
            float y2 = __shfl_sync(0xffffffffu, sc[kk][2], srcA + 2);
            float y3 = __shfl_sync(0xffffffffu, sc[kk][3], srcA + 2);
            unsigned aP[4];
            aP[0] = tf32_of(par ? x1 : x0);
            aP[1] = tf32_of(par ? x3 : x2);
            aP[2] = tf32_of(par ? y1 : y0);
            aP[3] = tf32_of(par ? y3 : y2);
            const unsigned* vr0 = vu + (kk * 8 + lr) * 72;
            const unsigned* vr1 = vu + (kk * 8 + lr + 4) * 72;
#pragma unroll
            for (int nt = 0; nt < 8; ++nt) {
                unsigned bv[2] = {vr0[nt * 8 + lq], vr1[nt * 8 + lq]};
                mma_tf32(O[nt], aP, bv);
            }
        }
    }

    const float inv0 = 1.f / l0, inv1 = 1.f / l1;
    if (qrow0 < cnt) {
        float* orow = g_ao + ((size_t)b * SEQ + ridx0) * DIM + h * HD;
#pragma unroll
        for (int nt = 0; nt < 8; ++nt) {
            int c = nt * 8 + lr * 2;
            *(float2*)&orow[c] = make_float2(O[nt][0] * inv0, O[nt][1] * inv0);
        }
    }
    if (qrow1 < cnt) {
        float* orow = g_ao + ((size_t)b * SEQ + ridx1) * DIM + h * HD;
#pragma unroll
        for (int nt = 0; nt < 8; ++nt) {
            int c = nt * 8 + lr * 2;
            *(float2*)&orow[c] = make_float2(O[nt][2] * inv1, O[nt][3] * inv1);
        }
    }
}

// ---------------------------------------------------------------------------
extern "C" void kernel_launch(void* const* d_in, const int* in_sizes, int n_in,
                              void* d_out, int out_size)
{
    const float* x      = (const float*)d_in[0];
    const int*   mask   = (const int*)d_in[1];
    const float* w_qkv  = (const float*)d_in[2];
    const float* w_proj = (const float*)d_in[3];
    const float* b_proj = (const float*)d_in[4];
    float*       out    = (float*)d_out;

    cudaFuncSetAttribute(attn_kernel,
        cudaFuncAttributeMaxDynamicSharedMemorySize, ATTN_SMEM_BYTES);

    compact_kernel<<<BATCH, 1024>>>(mask);

    dim3 g1(3 * DIM / 64, (BATCH * SEQ) / 128);
    gemm_tc<0><<<g1, 256>>>(x, w_qkv, nullptr, nullptr);

    gather_kernel<<<dim3(BATCH * HEADS, SEQ / 64), 256>>>();
    vsum_kernel<<<dim3(BATCH * HEADS, 8), 256>>>();

    dim3 g2(SEQ / 128, BATCH * HEADS);
    attn_kernel<<<g2, 256, ATTN_SMEM_BYTES>>>();

    fill_dead_kernel<<<dim3(BATCH, SEQ / 64), 256>>>(mask);

    dim3 g3(DIM / 64, (BATCH * SEQ) / 128);
    gemm_tc<1><<<g3, 256>>>(g_ao /* unused placeholder */, w_proj, b_proj, out);
}

// round 13
// speedup vs baseline: 1.2611x; 1.1389x over previous
#include <cuda_runtime.h>
#include <float.h>

#define BATCH 2
#define SEQ   4096
#define DIM   384
#define HEADS 6
#define HD    64
#define QK_SCALE 0.125f
#define NVP   32   // vsum partials per (b,h)

__device__ float g_q[BATCH * HEADS * SEQ * HD];
__device__ float g_k[BATCH * HEADS * SEQ * HD];   // pre-rounded tf32 (RNA)
__device__ float g_v[BATCH * HEADS * SEQ * HD];   // pre-rounded tf32 (RNA)
__device__ float g_kc[BATCH * HEADS * SEQ * HD];  // compacted K
__device__ float g_vc[BATCH * HEADS * SEQ * HD];  // compacted V
__device__ float g_ao[BATCH * SEQ * DIM];
__device__ int   g_qidx[BATCH * SEQ];
__device__ int   g_cnt[BATCH];
__device__ float g_vsump[BATCH * HEADS * NVP * HD];

__device__ __forceinline__ unsigned tf32_of(float f) {
    unsigned u; asm("cvt.rna.tf32.f32 %0, %1;" : "=r"(u) : "f"(f)); return u;
}
__device__ __forceinline__ float tf32r(float f) { return __uint_as_float(tf32_of(f)); }
__device__ __forceinline__ void mma_tf32(float* c, const unsigned* a, const unsigned* b) {
    asm volatile("mma.sync.aligned.m16n8k8.row.col.f32.tf32.tf32.f32 "
        "{%0,%1,%2,%3}, {%4,%5,%6,%7}, {%8,%9}, {%0,%1,%2,%3};"
        : "+f"(c[0]), "+f"(c[1]), "+f"(c[2]), "+f"(c[3])
        : "r"(a[0]), "r"(a[1]), "r"(a[2]), "r"(a[3]), "r"(b[0]), "r"(b[1]));
}
#define CP16(dst, src) \
    asm volatile("cp.async.cg.shared.global [%0], [%1], 16;" :: \
        "r"((unsigned)__cvta_generic_to_shared(dst)), "l"(src))

// ---------------------------------------------------------------------------
// GEMM, 2-term tf32 split: C += al*bh + ah*bh  (ah*bl dropped, ~2^-12 rel).
// SEL=0: qkv -> g_q/g_k/g_v (K,V RNA-rounded).  SEL=1: out = g_ao@w^T + bias.
// ---------------------------------------------------------------------------
template<int SEL>
__global__ __launch_bounds__(256, 2) void gemm_tc(
    const float* __restrict__ Ax, const float* __restrict__ w,
    const float* __restrict__ bias, float* __restrict__ out)
{
    __shared__ __align__(16) float As[2][128][20];
    __shared__ __align__(16) float Bs[2][64][20];

    const float* A = (SEL == 0) ? Ax : g_ao;

    const int bx = blockIdx.x, by = blockIdx.y;
    const int tid = threadIdx.x, wid = tid >> 5, l = tid & 31;
    const int lq = l >> 2, lr = l & 3;
    const int wm = (wid >> 1) * 32, wn = (wid & 1) * 32;
    const int m0 = by * 128, n0 = bx * 64;
    const int lrow = tid >> 2, lkc = (tid & 3) << 2;

    float C[2][4][4] = {};

    CP16(&As[0][lrow][lkc],      &A[(size_t)(m0 + lrow) * DIM + lkc]);
    CP16(&As[0][lrow + 64][lkc], &A[(size_t)(m0 + lrow + 64) * DIM + lkc]);
    CP16(&Bs[0][lrow][lkc],      &w[(size_t)(n0 + lrow) * DIM + lkc]);
    asm volatile("cp.async.commit_group;" ::: "memory");

    const int NITER = DIM / 16;
    for (int it = 0; it < NITER; ++it) {
        if (it + 1 < NITER) {
            int k0 = (it + 1) * 16, nb = (it + 1) & 1;
            CP16(&As[nb][lrow][lkc],      &A[(size_t)(m0 + lrow) * DIM + k0 + lkc]);
            CP16(&As[nb][lrow + 64][lkc], &A[(size_t)(m0 + lrow + 64) * DIM + k0 + lkc]);
            CP16(&Bs[nb][lrow][lkc],      &w[(size_t)(n0 + lrow) * DIM + k0 + lkc]);
            asm volatile("cp.async.commit_group;" ::: "memory");
            asm volatile("cp.async.wait_group 1;" ::: "memory");
        } else {
            asm volatile("cp.async.wait_group 0;" ::: "memory");
        }
        __syncthreads();
        const int buf = it & 1;
#pragma unroll
        for (int ks = 0; ks < 2; ++ks) {
            const int kb = ks * 8;
            unsigned ah[2][4], al[2][4], bh[4][2];
#pragma unroll
            for (int mt = 0; mt < 2; ++mt) {
                float a0 = As[buf][wm + mt * 16 + lq][kb + lr];
                float a1 = As[buf][wm + mt * 16 + lq + 8][kb + lr];
                float a2 = As[buf][wm + mt * 16 + lq][kb + lr + 4];
                float a3 = As[buf][wm + mt * 16 + lq + 8][kb + lr + 4];
                ah[mt][0] = tf32_of(a0); al[mt][0] = tf32_of(a0 - __uint_as_float(ah[mt][0]));
                ah[mt][1] = tf32_of(a1); al[mt][1] = tf32_of(a1 - __uint_as_float(ah[mt][1]));
                ah[mt][2] = tf32_of(a2); al[mt][2] = tf32_of(a2 - __uint_as_float(ah[mt][2]));
                ah[mt][3] = tf32_of(a3); al[mt][3] = tf32_of(a3 - __uint_as_float(ah[mt][3]));
            }
#pragma unroll
            for (int nt = 0; nt < 4; ++nt) {
                bh[nt][0] = tf32_of(Bs[buf][wn + nt * 8 + lq][kb + lr]);
                bh[nt][1] = tf32_of(Bs[buf][wn + nt * 8 + lq][kb + lr + 4]);
            }
#pragma unroll
            for (int mt = 0; mt < 2; ++mt)
#pragma unroll
                for (int nt = 0; nt < 4; ++nt) {
                    mma_tf32(C[mt][nt], al[mt], bh[nt]);
                    mma_tf32(C[mt][nt], ah[mt], bh[nt]);
                }
        }
        __syncthreads();
    }

    if (SEL == 0) {
        const int sel = bx / HEADS, h = bx % HEADS;
        float* dst = (sel == 0) ? g_q : (sel == 1 ? g_k : g_v);
        const bool rnd = (sel != 0);
#pragma unroll
        for (int mt = 0; mt < 2; ++mt) {
            int m = m0 + wm + mt * 16 + lq;
            float* p = dst + ((size_t)((m >> 12) * HEADS + h) * SEQ + (m & 4095)) * HD;
#pragma unroll
            for (int nt = 0; nt < 4; ++nt) {
                int n = wn + nt * 8 + lr * 2;
                float c0 = C[mt][nt][0], c1 = C[mt][nt][1];
                float c2 = C[mt][nt][2], c3 = C[mt][nt][3];
                if (rnd) { c0 = tf32r(c0); c1 = tf32r(c1); c2 = tf32r(c2); c3 = tf32r(c3); }
                *(float2*)&p[n]          = make_float2(c0, c1);
                *(float2*)&p[8 * HD + n] = make_float2(c2, c3);
            }
        }
    } else {
#pragma unroll
        for (int mt = 0; mt < 2; ++mt) {
            int m = m0 + wm + mt * 16 + lq;
#pragma unroll
            for (int nt = 0; nt < 4; ++nt) {
                int n = n0 + wn + nt * 8 + lr * 2;
                float b0 = bias[n], b1 = bias[n + 1];
                *(float2*)&out[(size_t)m * DIM + n] =
                    make_float2(C[mt][nt][0] + b0, C[mt][nt][1] + b1);
                *(float2*)&out[(size_t)(m + 8) * DIM + n] =
                    make_float2(C[mt][nt][2] + b0, C[mt][nt][3] + b1);
            }
        }
    }
}

// ---------------------------------------------------------------------------
// Compaction: ballot/popc warp scan (deterministic).
// ---------------------------------------------------------------------------
__global__ __launch_bounds__(1024) void compact_kernel(const int* __restrict__ mask)
{
    __shared__ int wsum[32];
    __shared__ int base;
    const int b = blockIdx.x, t = threadIdx.x;
    const int wid = t >> 5, lane = t & 31;
    if (t == 0) base = 0;
    __syncthreads();
    for (int pass = 0; pass < SEQ / 1024; ++pass) {
        int n = pass * 1024 + t;
        int m = (mask[b * SEQ + n] != 0) ? 1 : 0;
        unsigned bal = __ballot_sync(0xffffffffu, m);
        int wpre = __popc(bal & ((1u << lane) - 1u));
        if (lane == 0) wsum[wid] = __popc(bal);
        __syncthreads();
        if (wid == 0) {
            int v = wsum[lane];
#pragma unroll
            for (int off = 1; off < 32; off <<= 1) {
                int u = __shfl_up_sync(0xffffffffu, v, off);
                if (lane >= off) v += u;
            }
            wsum[lane] = v;
        }
        __syncthreads();
        int pre = (wid > 0 ? wsum[wid - 1] : 0) + wpre;
        if (m) g_qidx[b * SEQ + base + pre] = n;
        __syncthreads();
        if (t == 0) base += wsum[31];
        __syncthreads();
    }
    if (t == 0) g_cnt[b] = base;
}

// ---------------------------------------------------------------------------
__global__ __launch_bounds__(256) void gather_kernel()
{
    const int bh = blockIdx.x, tile = blockIdx.y;
    const int b = bh / HEADS;
    const int cnt = g_cnt[b];
    const int padded = (cnt + 63) & ~63;
    if (tile * 64 >= padded) return;
    const int t = threadIdx.x;
    const int row = tile * 64 + (t >> 2);
    const int seg = (t & 3) * 16;
    const float* kb = g_k + (size_t)bh * SEQ * HD;
    const float* vb = g_v + (size_t)bh * SEQ * HD;
    float* kc = g_kc + (size_t)bh * SEQ * HD;
    float* vc = g_vc + (size_t)bh * SEQ * HD;
    float4 kv[4], vv[4];
    if (row < cnt) {
        const int src = g_qidx[b * SEQ + row];
#pragma unroll
        for (int u = 0; u < 4; ++u) {
            kv[u] = *(const float4*)&kb[(size_t)src * HD + seg + u * 4];
            vv[u] = *(const float4*)&vb[(size_t)src * HD + seg + u * 4];
        }
    } else {
#pragma unroll
        for (int u = 0; u < 4; ++u) {
            kv[u] = make_float4(0.f, 0.f, 0.f, 0.f);
            vv[u] = make_float4(0.f, 0.f, 0.f, 0.f);
        }
    }
#pragma unroll
    for (int u = 0; u < 4; ++u) {
        *(float4*)&kc[(size_t)row * HD + seg + u * 4] = kv[u];
        *(float4*)&vc[(size_t)row * HD + seg + u * 4] = vv[u];
    }
}

// vsum partials: grid (12, NVP), each block sums SEQ/NVP = 128 rows.
__global__ __launch_bounds__(256) void vsum_kernel()
{
    __shared__ float sdata[256];
    const int bh = blockIdx.x, part = blockIdx.y;
    const int t = threadIdx.x;
    const int d = t & 63, g = t >> 6;     // 4 groups
    const float* vb = g_v + (size_t)bh * SEQ * HD;
    float s = 0.f;
    const int r0 = part * (SEQ / NVP);
    for (int n = r0 + g; n < r0 + SEQ / NVP; n += 4) s += vb[(size_t)n * HD + d];
    sdata[t] = s;
    __syncthreads();
    if (g == 0)
        g_vsump[(bh * NVP + part) * HD + d] =
            sdata[d] + sdata[64 + d] + sdata[128 + d] + sdata[192 + d];
}

// Dead rows -> g_ao = vsum / SEQ  (reduce the NVP partials, fixed order).
__global__ __launch_bounds__(256) void fill_dead_kernel(const int* __restrict__ mask)
{
    __shared__ float vsh[DIM];
    const int b = blockIdx.x, tile = blockIdx.y;
    const int t = threadIdx.x;
    const float inv = 1.0f / SEQ;
    for (int c = t; c < DIM; c += 256) {
        int bh = b * HEADS + (c >> 6), d = c & 63;
        float s = 0.f;
#pragma unroll
        for (int p = 0; p < NVP; ++p) s += g_vsump[(bh * NVP + p) * HD + d];
        vsh[c] = s * inv;
    }
    __syncthreads();
    for (int c = t; c < 64 * DIM; c += 256) {
        int row = tile * 64 + c / DIM;
        int col = c % DIM;
        if (mask[b * SEQ + row] != 0) continue;
        g_ao[((size_t)b * SEQ + row) * DIM + col] = vsh[col];
    }
}

// ---------------------------------------------------------------------------
// Flash attention over compacted rows/keys (unchanged, measured good).
// ---------------------------------------------------------------------------
#define KS_F (64 * 68)
#define VS_F (64 * 72)
#define STG  (KS_F + VS_F)
#define ATTN_SMEM_BYTES (3 * STG * 4)

__global__ __launch_bounds__(256, 2) void attn_kernel()
{
    extern __shared__ __align__(16) float sm[];

    const int qt = blockIdx.x, bh = blockIdx.y;
    const int b = bh / HEADS, h = bh % HEADS;
    const int cnt = g_cnt[b];
    if (qt * 128 >= cnt) return;

    const int tid = threadIdx.x, w = tid >> 5, l = tid & 31;
    const int lq = l >> 2, lr = l & 3;

    const float* qbase = g_q + (size_t)bh * SEQ * HD;
    const float* kbase = g_kc + (size_t)bh * SEQ * HD;
    const float* vbase = g_vc + (size_t)bh * SEQ * HD;

    const int qrow0 = qt * 128 + w * 16 + lq;
    const int qrow1 = qrow0 + 8;
    const int ridx0 = g_qidx[b * SEQ + (qrow0 < cnt ? qrow0 : 0)];
    const int ridx1 = g_qidx[b * SEQ + (qrow1 < cnt ? qrow1 : 0)];

    const int crow = tid >> 2;
    const int cbase = (tid & 3) * 16;

    unsigned aQ[8][4];
#pragma unroll
    for (int kk = 0; kk < 8; ++kk) {
        aQ[kk][0] = tf32_of(qbase[(size_t)ridx0 * HD + kk * 8 + lr] * QK_SCALE);
        aQ[kk][1] = tf32_of(qbase[(size_t)ridx1 * HD + kk * 8 + lr] * QK_SCALE);
        aQ[kk][2] = tf32_of(qbase[(size_t)ridx0 * HD + kk * 8 + lr + 4] * QK_SCALE);
        aQ[kk][3] = tf32_of(qbase[(size_t)ridx1 * HD + kk * 8 + lr + 4] * QK_SCALE);
    }

    float O[8][4] = {};
    float m0 = -FLT_MAX, m1 = -FLT_MAX, l0 = 0.f, l1 = 0.f;

    const int NT = (cnt + 63) >> 6;

    {
        float* ks = sm; float* vs = sm + KS_F;
#pragma unroll
        for (int u = 0; u < 4; ++u) {
            int off = cbase + u * 4;
            CP16(&ks[crow * 68 + off], &kbase[(size_t)crow * HD + off]);
            CP16(&vs[crow * 72 + off], &vbase[(size_t)crow * HD + off]);
        }
        asm volatile("cp.async.commit_group;" ::: "memory");
    }

    for (int kt = 0; kt < NT; ++kt) {
        const int s = kt % 3;
        const float* ksf = sm + s * STG;
        const unsigned* ku = (const unsigned*)ksf;
        const unsigned* vu = (const unsigned*)(ksf + KS_F);

        if (kt + 1 < NT) {
            float* ks2 = sm + ((kt + 1) % 3) * STG;
            float* vs2 = ks2 + KS_F;
            const size_t nb = (size_t)(kt + 1) * 64;
#pragma unroll
            for (int u = 0; u < 4; ++u) {
                int off = cbase + u * 4;
                CP16(&ks2[crow * 68 + off], &kbase[(nb + crow) * HD + off]);
                CP16(&vs2[crow * 72 + off], &vbase[(nb + crow) * HD + off]);
            }
            asm volatile("cp.async.commit_group;" ::: "memory");
            asm volatile("cp.async.wait_group 1;" ::: "memory");
        } else {
            asm volatile("cp.async.wait_group 0;" ::: "memory");
        }
        __syncthreads();

        float sc[8][4];
#pragma unroll
        for (int nt = 0; nt < 8; ++nt) {
            sc[nt][0] = sc[nt][1] = sc[nt][2] = sc[nt][3] = 0.f;
            const unsigned* krow = ku + (nt * 8 + lq) * 68;
#pragma unroll
            for (int kk = 0; kk < 8; ++kk) {
                unsigned bk[2] = {krow[kk * 8 + lr], krow[kk * 8 + lr + 4]};
                mma_tf32(sc[nt], aQ[kk], bk);
            }
        }

        const int ktbase = kt * 64;
        float t0 = -FLT_MAX, t1 = -FLT_MAX;
#pragma unroll
        for (int nt = 0; nt < 8; ++nt) {
            int c0 = ktbase + nt * 8 + lr * 2;
            bool v0 = c0 < cnt, v1 = (c0 + 1) < cnt;
            if (!v0) { sc[nt][0] = -FLT_MAX; sc[nt][2] = -FLT_MAX; }
            if (!v1) { sc[nt][1] = -FLT_MAX; sc[nt][3] = -FLT_MAX; }
            t0 = fmaxf(t0, fmaxf(sc[nt][0], sc[nt][1]));
            t1 = fmaxf(t1, fmaxf(sc[nt][2], sc[nt][3]));
        }
        t0 = fmaxf(t0, __shfl_xor_sync(0xffffffffu, t0, 1));
        t0 = fmaxf(t0, __shfl_xor_sync(0xffffffffu, t0, 2));
        t1 = fmaxf(t1, __shfl_xor_sync(0xffffffffu, t1, 1));
        t1 = fmaxf(t1, __shfl_xor_sync(0xffffffffu, t1, 2));

        float mn0 = fmaxf(m0, t0), mn1 = fmaxf(m1, t1);
        float al0 = __expf(m0 - mn0), al1 = __expf(m1 - mn1);
        m0 = mn0; m1 = mn1;

        float ps0 = 0.f, ps1 = 0.f;
#pragma unroll
        for (int nt = 0; nt < 8; ++nt) {
            sc[nt][0] = __expf(sc[nt][0] - mn0);
            sc[nt][1] = __expf(sc[nt][1] - mn0);
            sc[nt][2] = __expf(sc[nt][2] - mn1);
            sc[nt][3] = __expf(sc[nt][3] - mn1);
            ps0 += sc[nt][0] + sc[nt][1];
            ps1 += sc[nt][2] + sc[nt][3];
        }
        ps0 += __shfl_xor_sync(0xffffffffu, ps0, 1);
        ps0 += __shfl_xor_sync(0xffffffffu, ps0, 2);
        ps1 += __shfl_xor_sync(0xffffffffu, ps1, 1);
        ps1 += __shfl_xor_sync(0xffffffffu, ps1, 2);
        l0 = l0 * al0 + ps0;
        l1 = l1 * al1 + ps1;

#pragma unroll
        for (int nt = 0; nt < 8; ++nt) {
            O[nt][0] *= al0; O[nt][1] *= al0;
            O[nt][2] *= al1; O[nt][3] *= al1;
        }

        const int srcA = (l & ~3) + (lr >> 1);
        const bool par = (lr & 1) != 0;
#pragma unroll
        for (int kk = 0; kk < 8; ++kk) {
            float x0 = __shfl_sync(0xffffffffu, sc[kk][0], srcA);
            float x1 = __shfl_sync(0xffffffffu, sc[kk][1], srcA);
            float x2 = __shfl_sync(0xffffffffu, sc[kk][2], srcA);
            float x3 = __shfl_sync(0xffffffffu, sc[kk][3], srcA);
            float y0 = __shfl_sync(0xffffffffu, sc[kk][0], srcA + 2);
            float y1 = __shfl_sync(0xffffffffu, sc[kk][1], srcA + 2);
            float y2 = __shfl_sync(0xffffffffu, sc[kk][2], srcA + 2);
            float y3 = __shfl_sync(0xffffffffu, sc[kk][3], srcA + 2);
            unsigned aP[4];
            aP[0] = tf32_of(par ? x1 : x0);
            aP[1] = tf32_of(par ? x3 : x2);
            aP[2] = tf32_of(par ? y1 : y0);
            aP[3] = tf32_of(par ? y3 : y2);
            const unsigned* vr0 = vu + (kk * 8 + lr) * 72;
            const unsigned* vr1 = vu + (kk * 8 + lr + 4) * 72;
#pragma unroll
            for (int nt = 0; nt < 8; ++nt) {
                unsigned bv[2] = {vr0[nt * 8 + lq], vr1[nt * 8 + lq]};
                mma_tf32(O[nt], aP, bv);
            }
        }
    }

    const float inv0 = 1.f / l0, inv1 = 1.f / l1;
    if (qrow0 < cnt) {
        float* orow = g_ao + ((size_t)b * SEQ + ridx0) * DIM + h * HD;
#pragma unroll
        for (int nt = 0; nt < 8; ++nt) {
            int c = nt * 8 + lr * 2;
            *(float2*)&orow[c] = make_float2(O[nt][0] * inv0, O[nt][1] * inv0);
        }
    }
    if (qrow1 < cnt) {
        float* orow = g_ao + ((size_t)b * SEQ + ridx1) * DIM + h * HD;
#pragma unroll
        for (int nt = 0; nt < 8; ++nt) {
            int c = nt * 8 + lr * 2;
            *(float2*)&orow[c] = make_float2(O[nt][2] * inv1, O[nt][3] * inv1);
        }
    }
}

// ---------------------------------------------------------------------------
extern "C" void kernel_launch(void* const* d_in, const int* in_sizes, int n_in,
                              void* d_out, int out_size)
{
    const float* x      = (const float*)d_in[0];
    const int*   mask   = (const int*)d_in[1];
    const float* w_qkv  = (const float*)d_in[2];
    const float* w_proj = (const float*)d_in[3];
    const float* b_proj = (const float*)d_in[4];
    float*       out    = (float*)d_out;

    cudaFuncSetAttribute(attn_kernel,
        cudaFuncAttributeMaxDynamicSharedMemorySize, ATTN_SMEM_BYTES);

    compact_kernel<<<BATCH, 1024>>>(mask);

    dim3 g1(3 * DIM / 64, (BATCH * SEQ) / 128);
    gemm_tc<0><<<g1, 256>>>(x, w_qkv, nullptr, nullptr);

    gather_kernel<<<dim3(BATCH * HEADS, SEQ / 64), 256>>>();
    vsum_kernel<<<dim3(BATCH * HEADS, NVP), 256>>>();

    dim3 g2(SEQ / 128, BATCH * HEADS);
    attn_kernel<<<g2, 256, ATTN_SMEM_BYTES>>>();

    fill_dead_kernel<<<dim3(BATCH, SEQ / 64), 256>>>(mask);

    dim3 g3(DIM / 64, (BATCH * SEQ) / 128);
    gemm_tc<1><<<g3, 256>>>(nullptr, w_proj, b_proj, out);
}